// round 10
// baseline (speedup 1.0000x reference)
#include <cuda_runtime.h>
#include <cuda_fp16.h>
#include <math.h>

#define NSPAT (64*64*64)
#define OFFSETS_OFF (2*5*NSPAT)
#define LOSS_OFF (16*NSPAT)

// B fragments: [tap(27)][kcp(2)][lane(32)] -> uint4
__device__ __align__(16) uint4 g_btab[1728];
__device__ unsigned long long g_key[128];   // per (b,gt): (d_bits<<32)|anchor
__device__ double g_loss[1];
__device__ unsigned g_tile;

__device__ __forceinline__ float logsig_f(float x) {
    return fminf(x, 0.f) - __logf(1.f + __expf(-fabsf(x)));
}
// focal term for target=0: p^2 * (-log(1-p))
__device__ __forceinline__ float focal0(float x) {
    float p = 1.f / (1.f + __expf(-x));
    return -p * p * logsig_f(-x);
}

// ---------------------------------------------------------------------------
// Precompute packed fp16 B fragments once
// ---------------------------------------------------------------------------
__global__ void build_tab_kernel(const float* __restrict__ cls_w,
                                 const float* __restrict__ off_w) {
    int i = blockIdx.x * 256 + threadIdx.x;     // 0..1727
    if (i >= 1728) return;
    int lane = i & 31, kcp = (i >> 5) & 1, tap = i >> 6;
    int n = lane >> 2, k0 = (lane & 3) * 2;
    const float* w = (n < 5) ? (cls_w + n * 1728) : (off_w + (n - 5) * 1728);
    uint4 r;
    {
        int kk = (2 * kcp) * 16 + k0;
        r.x = (unsigned)__half_as_ushort(__float2half_rn(w[kk * 27 + tap]))
            | ((unsigned)__half_as_ushort(__float2half_rn(w[(kk + 1) * 27 + tap])) << 16);
        r.y = (unsigned)__half_as_ushort(__float2half_rn(w[(kk + 8) * 27 + tap]))
            | ((unsigned)__half_as_ushort(__float2half_rn(w[(kk + 9) * 27 + tap])) << 16);
    }
    {
        int kk = (2 * kcp + 1) * 16 + k0;
        r.z = (unsigned)__half_as_ushort(__float2half_rn(w[kk * 27 + tap]))
            | ((unsigned)__half_as_ushort(__float2half_rn(w[(kk + 1) * 27 + tap])) << 16);
        r.w = (unsigned)__half_as_ushort(__float2half_rn(w[(kk + 8) * 27 + tap]))
            | ((unsigned)__half_as_ushort(__float2half_rn(w[(kk + 9) * 27 + tap])) << 16);
    }
    g_btab[i] = r;
}

__global__ void init_kernel() {
    int t = threadIdx.x;
    if (t < 128) g_key[t] = 0xFFFFFFFFFFFFFFFFull;
    if (t == 128) g_loss[0] = 0.0;
    if (t == 129) g_tile = 0u;
}

// ---------------------------------------------------------------------------
// Fused conv + argmin + default loss
// ---------------------------------------------------------------------------
__device__ __forceinline__ void writeOut(float* out, int b, int n, int m, float v) {
    if (n < 5) out[(size_t)(b * 5 + n) * NSPAT + m] = v;
    else       out[OFFSETS_OFF + (size_t)(b * 3 + (n - 5)) * NSPAT + m] = v;
}

#define MMA_F16(ac, a0,a1,a2,a3, b0,b1) \
    asm volatile("mma.sync.aligned.m16n8k16.row.col.f32.f16.f16.f32 " \
        "{%0,%1,%2,%3}, {%4,%5,%6,%7}, {%8,%9}, {%0,%1,%2,%3};" \
        : "+f"(ac[0]), "+f"(ac[1]), "+f"(ac[2]), "+f"(ac[3]) \
        : "r"(a0), "r"(a1), "r"(a2), "r"(a3), "r"(b0), "r"(b1))

#define SM_BUF 8192
#define SM_TAB 24576                /* uint4 tab 27648B */
#define SM_EDGE (SM_TAB + 27648)    /* 52224: sPe 1KB + sMe 1KB */
#define SM_GT   (SM_EDGE + 2048)    /* 54272: 64 float4 = 1KB */
#define SM_WKEY (SM_GT + 1024)      /* 55296: 8 warps x 64 u64 = 4KB */
#define SM_TILE (SM_WKEY + 4096)    /* 59392 */
#define SM_TOTAL (SM_TILE + 16)
#define NTILES 1024
#define NBLK 296
#define FULLM 0xFFFFFFFFu

extern __shared__ unsigned char s_dyn[];

__global__ __launch_bounds__(256, 2) void conv_mma_kernel(
        const float* __restrict__ feat, const float* __restrict__ labels,
        const float* __restrict__ cls_b, const float* __restrict__ off_b,
        float* __restrict__ out) {
    int tid = threadIdx.x, lane = tid & 31, warp = tid >> 5;
    int q = warp & 3, riL = warp >> 2;
    int j = lane & 3;

    unsigned sbase = (unsigned)__cvta_generic_to_shared(s_dyn);
    const uint4* s_tab = (const uint4*)(s_dyn + SM_TAB);
    float* sPe = (float*)(s_dyn + SM_EDGE);
    float* sMe = (float*)(s_dyn + SM_EDGE + 1024);
    float4* s_gt = (float4*)(s_dyn + SM_GT);
    unsigned long long* s_wkey = (unsigned long long*)(s_dyn + SM_WKEY);
    unsigned* s_tile = (unsigned*)(s_dyn + SM_TILE);

    {
        uint4* dst = (uint4*)(s_dyn + SM_TAB);
        for (int i = tid; i < 1728; i += 256) dst[i] = g_btab[i];
    }

    int n0 = j * 2;
    float bi0 = (n0 < 5)     ? cls_b[n0]     : off_b[n0 - 5];
    float bi1 = (n0 + 1 < 5) ? cls_b[n0 + 1] : off_b[n0 - 4];

    const float* featW = feat + (size_t)(warp * 8) * NSPAT + 2 * lane;
    double lacc = 0.0;

#define LDG_ROW(ZZ_, YY_, RR_) do { \
    int zp_ = z0 + (ZZ_) - 1, yp_ = y0 + (YY_) - 1; \
    if (((unsigned)zp_ < 64u) & ((unsigned)yp_ < 64u)) { \
        const float* p_ = featW + (size_t)b * 64 * NSPAT + zp_ * 4096 + yp_ * 64; \
        _Pragma("unroll") \
        for (int cc_ = 0; cc_ < 8; cc_++) RR_[cc_] = *(const float2*)(p_ + (size_t)cc_ * NSPAT); \
    } else { \
        _Pragma("unroll") \
        for (int cc_ = 0; cc_ < 8; cc_++) RR_[cc_] = make_float2(0.f, 0.f); \
    } \
} while (0)

#define STS_ROW(BUF_, RR_) do { \
    __half2 h0_[4], h1_[4]; \
    _Pragma("unroll") \
    for (int j_ = 0; j_ < 4; j_++) { \
        h0_[j_] = __floats2half2_rn(RR_[2*j_].x, RR_[2*j_+1].x); \
        h1_[j_] = __floats2half2_rn(RR_[2*j_].y, RR_[2*j_+1].y); \
    } \
    int v0_ = 2 * lane, v1_ = 2 * lane + 1; \
    *(uint4*)(s_dyn + (BUF_) * SM_BUF + (v0_ * 8 + (warp ^ (v0_ & 7))) * 16) = *(uint4*)h0_; \
    *(uint4*)(s_dyn + (BUF_) * SM_BUF + (v1_ * 8 + (warp ^ (v1_ & 7))) * 16) = *(uint4*)h1_; \
} while (0)

    for (;;) {
        if (tid == 0) s_tile[0] = atomicAdd(&g_tile, 1u);
        __syncthreads();
        unsigned t = s_tile[0];
        if (t >= NTILES) break;

        int z0 = (t & 31) * 2;
        int y0 = ((t >> 5) & 15) * 4;
        int b  = t >> 9;

        // stage GT data (centers + 1/(2 sigma^2))
        if (tid < 64) {
            float tz = labels[(b * 5 + 0) * 64 + tid];
            float ty = labels[(b * 5 + 1) * 64 + tid];
            float tx = labels[(b * 5 + 2) * 64 + tid];
            float sg = labels[(b * 5 + 4) * 64 + tid];
            s_gt[tid] = make_float4(tz, ty, tx, 1.f / (2.f * sg * sg));
        }

        float acc[4][3][4];
#pragma unroll
        for (int s = 0; s < 4; s++)
#pragma unroll
            for (int jj = 0; jj < 3; jj++) {
                float v0 = (jj == 1) ? bi0 : 0.f, v1 = (jj == 1) ? bi1 : 0.f;
                acc[s][jj][0] = v0; acc[s][jj][1] = v1; acc[s][jj][2] = v0; acc[s][jj][3] = v1;
            }

        float2 rA[8], rB[8];
        LDG_ROW(0, 0, rA);
        LDG_ROW(0, 1, rB);
        STS_ROW(0, rA);
        STS_ROW(1, rB);
        LDG_ROW(0, 2, rA);

#pragma unroll 1
        for (int zz = 0; zz < 4; zz++) {
#pragma unroll
            for (int yy = 0; yy < 6; yy++) {
                __syncthreads();
                if (!(zz == 3 && yy >= 4)) {
                    if (yy & 1) STS_ROW((yy + 2) % 3, rB);
                    else        STS_ROW((yy + 2) % 3, rA);
                }
                if (!(zz == 3 && yy >= 3)) {
                    if (yy & 1) { if (yy + 3 < 6) LDG_ROW(zz, yy + 3, rA); else LDG_ROW(zz + 1, yy - 3, rA); }
                    else        { if (yy + 3 < 6) LDG_ROW(zz, yy + 3, rB); else LDG_ROW(zz + 1, yy - 3, rB); }
                }

                bool active = riL ? (yy >= 1) : (yy <= 4);
                if (active) {
                    unsigned abase = sbase + (unsigned)((yy % 3) * SM_BUF);
#pragma unroll
                    for (int kcp = 0; kcp < 2; kcp++) {
                        int vs = 16 * q + (lane & 15);
                        unsigned ch0 = (unsigned)(4 * kcp + (lane >> 4));
                        unsigned ch1 = ch0 + 2;
                        unsigned adr0 = abase + (unsigned)((vs * 8 + (ch0 ^ (vs & 7))) * 16);
                        unsigned adr1 = abase + (unsigned)((vs * 8 + (ch1 ^ (vs & 7))) * 16);
                        unsigned a0, a1, a2, a3, c0, c1, c2, c3;
                        asm volatile("ldmatrix.sync.aligned.m8n8.x4.shared.b16 {%0,%1,%2,%3}, [%4];"
                            : "=r"(a0), "=r"(a1), "=r"(a2), "=r"(a3) : "r"(adr0));
                        asm volatile("ldmatrix.sync.aligned.m8n8.x4.shared.b16 {%0,%1,%2,%3}, [%4];"
                            : "=r"(c0), "=r"(c1), "=r"(c2), "=r"(c3) : "r"(adr1));
#pragma unroll
                        for (int zi = 0; zi < 2; zi++) {
                            unsigned dz = (unsigned)(zz - zi);
                            if (dz > 2u) continue;
#pragma unroll
                            for (int rih = 0; rih < 2; rih++) {
                                int y = rih * 2 + riL;
                                unsigned dy = (unsigned)(yy - y);
                                if (dy > 2u) continue;
                                int tb = (int)(dz * 9u + dy * 3u);
#pragma unroll
                                for (int dx = 0; dx < 3; dx++) {
                                    uint4 B = s_tab[((tb + dx) * 2 + kcp) * 32 + lane];
                                    MMA_F16(acc[zi * 2 + rih][dx], a0, a1, a2, a3, B.x, B.y);
                                    MMA_F16(acc[zi * 2 + rih][dx], c0, c1, c2, c3, B.z, B.w);
                                }
                            }
                        }
                    }
                }
            }
        }
        __syncthreads();

        // edge staging for shift-recombination
#pragma unroll
        for (int s = 0; s < 4; s++) {
            int e = ((s * 2 + riL) * 4 + q) * 8 + j * 2;
            if (lane >= 28) { sPe[e] = acc[s][0][2]; sPe[e + 1] = acc[s][0][3]; }
            if (lane < 4)   { sMe[e] = acc[s][2][0]; sMe[e + 1] = acc[s][2][1]; }
        }
        __syncthreads();

        float pzv[8], pyv[8], pxv[8];
        int   mBase[4];
        float lsum = 0.f, rsum = 0.f;
        int grp = lane & ~3;

#pragma unroll
        for (int s = 0; s < 4; s++) {
            float* P = acc[s][0]; float* C = acc[s][1]; float* M = acc[s][2];
            float p0s = __shfl_up_sync(FULLM, P[0], 4);
            float p1s = __shfl_up_sync(FULLM, P[1], 4);
            float p2s = __shfl_up_sync(FULLM, P[2], 4);
            float p3s = __shfl_up_sync(FULLM, P[3], 4);
            float p0h = __shfl_sync(FULLM, P[0], 28 + j);
            float p1h = __shfl_sync(FULLM, P[1], 28 + j);
            float m0s = __shfl_down_sync(FULLM, M[0], 4);
            float m1s = __shfl_down_sync(FULLM, M[1], 4);
            float m2s = __shfl_down_sync(FULLM, M[2], 4);
            float m3s = __shfl_down_sync(FULLM, M[3], 4);
            float m2h = __shfl_sync(FULLM, M[2], j);
            float m3h = __shfl_sync(FULLM, M[3], j);
            if (lane < 4) {
                p2s = p0h; p3s = p1h;
                int e = ((s * 2 + riL) * 4 + (q - 1)) * 8 + j * 2;
                p0s = (q > 0) ? sPe[e]     : 0.f;
                p1s = (q > 0) ? sPe[e + 1] : 0.f;
            }
            if (lane >= 28) {
                int jj2 = lane - 28;
                m0s = m2h; m1s = m3h;
                int e = ((s * 2 + riL) * 4 + (q + 1)) * 8 + jj2 * 2;
                m2s = (q < 3) ? sMe[e]     : 0.f;
                m3s = (q < 3) ? sMe[e + 1] : 0.f;
            }
            float d0 = C[0] + p0s + m0s;
            float d1 = C[1] + p1s + m1s;
            float d2 = C[2] + p2s + m2s;
            float d3 = C[3] + p3s + m3s;

            int zi = s >> 1, ri = (s & 1) * 2 + riL;
            int mg = (z0 + zi) * 4096 + (y0 + ri) * 64 + 16 * q + (lane >> 2);
            mBase[s] = mg;
            writeOut(out, b, n0,     mg,     d0);
            writeOut(out, b, n0 + 1, mg,     d1);
            writeOut(out, b, n0,     mg + 8, d2);
            writeOut(out, b, n0 + 1, mg + 8, d3);

            // default focal (assigned = -1): class channels only
            if (j < 2)       lsum += focal0(d0) + focal0(d1) + focal0(d2) + focal0(d3);
            else if (j == 2) lsum += focal0(d0) + focal0(d2);

            // gather offsets -> positions for this slot's 2 anchors
            float oz0 = __shfl_sync(FULLM, d1, grp + 2);
            float oz1 = __shfl_sync(FULLM, d3, grp + 2);
            float oy0 = __shfl_sync(FULLM, d0, grp + 3);
            float oy1 = __shfl_sync(FULLM, d2, grp + 3);
            float ox0 = __shfl_sync(FULLM, d1, grp + 3);
            float ox1 = __shfl_sync(FULLM, d3, grp + 3);
            float az = ((z0 + zi) + 0.5f) * 32.f;
            float ay = ((y0 + ri) + 0.5f) * 32.f;
            float ax = ((16 * q + (lane >> 2)) + 0.5f) * 32.f;
            pzv[s * 2]     = az + oz0;  pzv[s * 2 + 1] = az + oz1;
            pyv[s * 2]     = ay + oy0;  pyv[s * 2 + 1] = ay + oy1;
            pxv[s * 2]     = ax + ox0;  pxv[s * 2 + 1] = ax + ox1 + 256.f;
        }
        // fix: anchor +8 x-shift for pz/py too? no: only x changes. pxv[k=1] handled above.

        // GT loop: lane j handles n = i*4 + j
#pragma unroll 1
        for (int i = 0; i < 16; i++) {
            int n = i * 4 + j;
            float4 g = s_gt[n];
            unsigned long long best = 0xFFFFFFFFFFFFFFFFull;
#pragma unroll
            for (int s = 0; s < 4; s++)
#pragma unroll
                for (int k = 0; k < 2; k++) {
                    float dz = pzv[s * 2 + k] - g.x;
                    float dy = pyv[s * 2 + k] - g.y;
                    float dx = pxv[s * 2 + k] - g.z;
                    float d = __fmaf_rn(dz, dz, __fmaf_rn(dy, dy, dx * dx));
                    unsigned m = (unsigned)(mBase[s] + k * 8);
                    unsigned long long key =
                        ((unsigned long long)__float_as_uint(d) << 32) | m;
                    best = min(best, key);
                    if (i == 0 && j == 0)       // n == 0: reg default term
                        rsum += 1.f - __expf(-d * g.w);
                }
            best = min(best, __shfl_xor_sync(FULLM, best, 4));
            best = min(best, __shfl_xor_sync(FULLM, best, 8));
            best = min(best, __shfl_xor_sync(FULLM, best, 16));
            if (lane < 4) s_wkey[warp * 64 + n] = best;
        }
        __syncthreads();

        if (tid < 64) {
            unsigned long long v = s_wkey[tid];
#pragma unroll
            for (int w = 1; w < 8; w++) v = min(v, s_wkey[w * 64 + tid]);
            atomicMin(&g_key[b * 64 + tid], v);
        }
        lacc += (double)lsum + (double)rsum;
    }

    // block-reduce loss sum
    __syncthreads();
    double* sdd = (double*)s_dyn;
    sdd[tid] = lacc;
    __syncthreads();
    for (int s = 128; s > 0; s >>= 1) {
        if (tid < s) sdd[tid] += sdd[tid + s];
        __syncthreads();
    }
    if (tid == 0) atomicAdd(&g_loss[0], sdd[0]);
}

// ---------------------------------------------------------------------------
// Fixup: corrections for matched anchors (<=128)
// ---------------------------------------------------------------------------
__global__ __launch_bounds__(128) void fixup_kernel(const float* __restrict__ out,
                                                    const float* __restrict__ labels) {
    int tid = threadIdx.x;
    int b = tid >> 6, n = tid & 63;

    __shared__ int   s_m[128];
    __shared__ double sd[128];

    float c = labels[(b * 5 + 3) * 64 + n];
    bool valid = (c >= -0.5f);
    int m = (int)(unsigned)(g_key[b * 64 + n] & 0xFFFFFFFFull);
    s_m[tid] = valid ? m : -1;
    __syncthreads();

    double corr = 0.0;
    if (valid) {
        bool winner = true;
        for (int k = n + 1; k < 64; k++)
            if (s_m[b * 64 + k] == m) { winner = false; break; }
        if (winner) {
            int a = (int)c;
            float x = out[(size_t)(b * 5 + a) * NSPAT + m];
            float p = 1.f / (1.f + __expf(-x));
            float t1 = -(1.f - p) * (1.f - p) * logsig_f(x);
            float t0 = focal0(x);
            // remove default reg term for this anchor
            const float* off = out + OFFSETS_OFF + (size_t)b * 3 * NSPAT;
            int z = m >> 12, y = (m >> 6) & 63, xx = m & 63;
            float pz = (z + 0.5f) * 32.f + off[m];
            float py = (y + 0.5f) * 32.f + off[NSPAT + m];
            float px = (xx + 0.5f) * 32.f + off[2 * NSPAT + m];
            float tz = labels[(b * 5 + 0) * 64];
            float ty = labels[(b * 5 + 1) * 64];
            float tx = labels[(b * 5 + 2) * 64];
            float sg = labels[(b * 5 + 4) * 64];
            float inv0 = 1.f / (2.f * sg * sg);
            float dz = pz - tz, dy = py - ty, dx = px - tx;
            float d = __fmaf_rn(dz, dz, __fmaf_rn(dy, dy, dx * dx));
            float r = 1.f - __expf(-d * inv0);
            corr = (double)(t1 - t0) - (double)r;
        }
    }
    sd[tid] = corr;
    __syncthreads();
    for (int s = 64; s > 0; s >>= 1) {
        if (tid < s) sd[tid] += sd[tid + s];
        __syncthreads();
    }
    if (tid == 0) atomicAdd(&g_loss[0], sd[0]);
}

__global__ void finalize_kernel(const void* __restrict__ nitems, float* __restrict__ out) {
    long long iv = ((const int*)nitems)[0];
    float     fv = ((const float*)nitems)[0];
    double n = (iv >= 1 && iv <= 1048576) ? (double)iv : (double)fv;
    out[LOSS_OFF] = (float)(g_loss[0] / n);
}

// ---------------------------------------------------------------------------
extern "C" void kernel_launch(void* const* d_in, const int* in_sizes, int n_in,
                              void* d_out, int out_size) {
    const float* feat   = (const float*)d_in[0];
    const float* labels = (const float*)d_in[1];
    const float* cls_w  = (const float*)d_in[2];
    const float* cls_b  = (const float*)d_in[3];
    const float* off_w  = (const float*)d_in[4];
    const float* off_b  = (const float*)d_in[5];
    float* out = (float*)d_out;

    cudaFuncSetAttribute(conv_mma_kernel, cudaFuncAttributeMaxDynamicSharedMemorySize, SM_TOTAL);

    build_tab_kernel<<<7, 256>>>(cls_w, off_w);
    init_kernel<<<1, 256>>>();
    conv_mma_kernel<<<NBLK, 256, SM_TOTAL>>>(feat, labels, cls_b, off_b, out);
    fixup_kernel<<<1, 128>>>(out, labels);
    finalize_kernel<<<1, 1>>>(d_in[6], out);
}

// round 11
// speedup vs baseline: 1.3821x; 1.3821x over previous
#include <cuda_runtime.h>
#include <cuda_fp16.h>
#include <math.h>

#define NSPAT (64*64*64)
#define OFFSETS_OFF (2*5*NSPAT)
#define LOSS_OFF (16*NSPAT)

// B fragments: [tap(27)][kcp(2)][lane(32)] -> uint4 {kc lo,hi | kc+1 lo,hi}
__device__ __align__(16) uint4 g_btab[1728];
__device__ unsigned long long g_key[128];
__device__ double g_loss[1];
__device__ unsigned g_tile;

// ---------------------------------------------------------------------------
// Precompute packed fp16 B fragments once (+ global state init)
// ---------------------------------------------------------------------------
__global__ void build_tab_kernel(const float* __restrict__ cls_w,
                                 const float* __restrict__ off_w) {
    int i = blockIdx.x * 256 + threadIdx.x;     // 0..1791
    if (blockIdx.x == 0) {
        int t = threadIdx.x;
        if (t < 128) g_key[t] = 0xFFFFFFFFFFFFFFFFull;
        if (t == 128) g_loss[0] = 0.0;
        if (t == 129) g_tile = 0u;
    }
    if (i >= 1728) return;
    int lane = i & 31, kcp = (i >> 5) & 1, tap = i >> 6;
    int n = lane >> 2, k0 = (lane & 3) * 2;
    const float* w = (n < 5) ? (cls_w + n * 1728) : (off_w + (n - 5) * 1728);
    uint4 r;
    {
        int kk = (2 * kcp) * 16 + k0;
        r.x = (unsigned)__half_as_ushort(__float2half_rn(w[kk * 27 + tap]))
            | ((unsigned)__half_as_ushort(__float2half_rn(w[(kk + 1) * 27 + tap])) << 16);
        r.y = (unsigned)__half_as_ushort(__float2half_rn(w[(kk + 8) * 27 + tap]))
            | ((unsigned)__half_as_ushort(__float2half_rn(w[(kk + 9) * 27 + tap])) << 16);
    }
    {
        int kk = (2 * kcp + 1) * 16 + k0;
        r.z = (unsigned)__half_as_ushort(__float2half_rn(w[kk * 27 + tap]))
            | ((unsigned)__half_as_ushort(__float2half_rn(w[(kk + 1) * 27 + tap])) << 16);
        r.w = (unsigned)__half_as_ushort(__float2half_rn(w[(kk + 8) * 27 + tap]))
            | ((unsigned)__half_as_ushort(__float2half_rn(w[(kk + 9) * 27 + tap])) << 16);
    }
    g_btab[i] = r;
}

// ---------------------------------------------------------------------------
// Fused conv: direct fp32 NCDHW load + fp16 convert + shift-accumulator MMA
// ---------------------------------------------------------------------------
__device__ __forceinline__ void writeOut(float* out, int b, int n, int m, float v) {
    if (n < 5) out[(size_t)(b * 5 + n) * NSPAT + m] = v;
    else       out[OFFSETS_OFF + (size_t)(b * 3 + (n - 5)) * NSPAT + m] = v;
}

#define MMA_F16(ac, a0,a1,a2,a3, b0,b1) \
    asm volatile("mma.sync.aligned.m16n8k16.row.col.f32.f16.f16.f32 " \
        "{%0,%1,%2,%3}, {%4,%5,%6,%7}, {%8,%9}, {%0,%1,%2,%3};" \
        : "+f"(ac[0]), "+f"(ac[1]), "+f"(ac[2]), "+f"(ac[3]) \
        : "r"(a0), "r"(a1), "r"(a2), "r"(a3), "r"(b0), "r"(b1))

#define SM_BUF 8192                 /* 64 voxels * 64ch * 2B */
#define SM_TAB (3*SM_BUF)           /* 24576 */
#define SM_EDGE (SM_TAB + 27648)    /* 52224 */
#define SM_TOTAL (SM_EDGE + 2048 + 16)
#define NTILES 1024
#define NBLK 296
#define FULLM 0xFFFFFFFFu

extern __shared__ unsigned char s_dyn[];

__global__ __launch_bounds__(256, 2) void conv_mma_kernel(
        const float* __restrict__ feat,
        const float* __restrict__ cls_b, const float* __restrict__ off_b,
        float* __restrict__ out) {
    int tid = threadIdx.x, lane = tid & 31, warp = tid >> 5;
    int q = warp & 3, riL = warp >> 2;

    unsigned sbase = (unsigned)__cvta_generic_to_shared(s_dyn);
    const uint4* s_tab = (const uint4*)(s_dyn + SM_TAB);
    float* sPe = (float*)(s_dyn + SM_EDGE);
    float* sMe = (float*)(s_dyn + SM_EDGE + 1024);
    unsigned* s_tile = (unsigned*)(s_dyn + SM_EDGE + 2048);

    {
        uint4* dst = (uint4*)(s_dyn + SM_TAB);
        for (int i = tid; i < 1728; i += 256) dst[i] = g_btab[i];
    }

    int n0 = (lane & 3) * 2;
    float bi0 = (n0 < 5)     ? cls_b[n0]     : off_b[n0 - 5];
    float bi1 = (n0 + 1 < 5) ? cls_b[n0 + 1] : off_b[n0 - 4];

    const float* featW = feat + (size_t)(warp * 8) * NSPAT + 2 * lane;

#define LDG_ROW(ZZ_, YY_, RR_) do { \
    int zp_ = z0 + (ZZ_) - 1, yp_ = y0 + (YY_) - 1; \
    if (((unsigned)zp_ < 64u) & ((unsigned)yp_ < 64u)) { \
        const float* p_ = featW + (size_t)b * 64 * NSPAT + zp_ * 4096 + yp_ * 64; \
        _Pragma("unroll") \
        for (int cc_ = 0; cc_ < 8; cc_++) RR_[cc_] = *(const float2*)(p_ + (size_t)cc_ * NSPAT); \
    } else { \
        _Pragma("unroll") \
        for (int cc_ = 0; cc_ < 8; cc_++) RR_[cc_] = make_float2(0.f, 0.f); \
    } \
} while (0)

#define STS_ROW(BUF_, RR_) do { \
    __half2 h0_[4], h1_[4]; \
    _Pragma("unroll") \
    for (int j_ = 0; j_ < 4; j_++) { \
        h0_[j_] = __floats2half2_rn(RR_[2*j_].x, RR_[2*j_+1].x); \
        h1_[j_] = __floats2half2_rn(RR_[2*j_].y, RR_[2*j_+1].y); \
    } \
    int v0_ = 2 * lane, v1_ = 2 * lane + 1; \
    *(uint4*)(s_dyn + (BUF_) * SM_BUF + (v0_ * 8 + (warp ^ (v0_ & 7))) * 16) = *(uint4*)h0_; \
    *(uint4*)(s_dyn + (BUF_) * SM_BUF + (v1_ * 8 + (warp ^ (v1_ & 7))) * 16) = *(uint4*)h1_; \
} while (0)

    for (;;) {
        if (tid == 0) s_tile[0] = atomicAdd(&g_tile, 1u);
        __syncthreads();
        unsigned t = s_tile[0];
        if (t >= NTILES) break;

        int z0 = (t & 31) * 2;
        int y0 = ((t >> 5) & 15) * 4;
        int b  = t >> 9;

        float acc[4][3][4];
#pragma unroll
        for (int s = 0; s < 4; s++)
#pragma unroll
            for (int j = 0; j < 3; j++) {
                float v0 = (j == 1) ? bi0 : 0.f, v1 = (j == 1) ? bi1 : 0.f;
                acc[s][j][0] = v0; acc[s][j][1] = v1; acc[s][j][2] = v0; acc[s][j][3] = v1;
            }

        float2 rA[8], rB[8];
        LDG_ROW(0, 0, rA);
        LDG_ROW(0, 1, rB);
        STS_ROW(0, rA);
        STS_ROW(1, rB);
        LDG_ROW(0, 2, rA);

#pragma unroll 1
        for (int zz = 0; zz < 4; zz++) {
#pragma unroll
            for (int yy = 0; yy < 6; yy++) {
                __syncthreads();
                if (!(zz == 3 && yy >= 4)) {
                    if (yy & 1) STS_ROW((yy + 2) % 3, rB);
                    else        STS_ROW((yy + 2) % 3, rA);
                }
                if (!(zz == 3 && yy >= 3)) {
                    if (yy & 1) { if (yy + 3 < 6) LDG_ROW(zz, yy + 3, rA); else LDG_ROW(zz + 1, yy - 3, rA); }
                    else        { if (yy + 3 < 6) LDG_ROW(zz, yy + 3, rB); else LDG_ROW(zz + 1, yy - 3, rB); }
                }

                bool active = riL ? (yy >= 1) : (yy <= 4);
                if (active) {
                    unsigned abase = sbase + (unsigned)((yy % 3) * SM_BUF);
#pragma unroll
                    for (int kcp = 0; kcp < 2; kcp++) {
                        int vs = 16 * q + (lane & 15);
                        unsigned ch0 = (unsigned)(4 * kcp + (lane >> 4));
                        unsigned ch1 = ch0 + 2;
                        unsigned adr0 = abase + (unsigned)((vs * 8 + (ch0 ^ (vs & 7))) * 16);
                        unsigned adr1 = abase + (unsigned)((vs * 8 + (ch1 ^ (vs & 7))) * 16);
                        unsigned a0, a1, a2, a3, c0, c1, c2, c3;
                        asm volatile("ldmatrix.sync.aligned.m8n8.x4.shared.b16 {%0,%1,%2,%3}, [%4];"
                            : "=r"(a0), "=r"(a1), "=r"(a2), "=r"(a3) : "r"(adr0));
                        asm volatile("ldmatrix.sync.aligned.m8n8.x4.shared.b16 {%0,%1,%2,%3}, [%4];"
                            : "=r"(c0), "=r"(c1), "=r"(c2), "=r"(c3) : "r"(adr1));
#pragma unroll
                        for (int zi = 0; zi < 2; zi++) {
                            unsigned dz = (unsigned)(zz - zi);
                            if (dz > 2u) continue;
#pragma unroll
                            for (int rih = 0; rih < 2; rih++) {
                                int y = rih * 2 + riL;
                                unsigned dy = (unsigned)(yy - y);
                                if (dy > 2u) continue;
                                int tb = (int)(dz * 9u + dy * 3u);
#pragma unroll
                                for (int dx = 0; dx < 3; dx++) {
                                    uint4 B = s_tab[((tb + dx) * 2 + kcp) * 32 + lane];
                                    MMA_F16(acc[zi * 2 + rih][dx], a0, a1, a2, a3, B.x, B.y);
                                    MMA_F16(acc[zi * 2 + rih][dx], c0, c1, c2, c3, B.z, B.w);
                                }
                            }
                        }
                    }
                }
            }
        }
        __syncthreads();

        int j = lane & 3;
#pragma unroll
        for (int s = 0; s < 4; s++) {
            int e = ((s * 2 + riL) * 4 + q) * 8 + j * 2;
            if (lane >= 28) { sPe[e] = acc[s][0][2]; sPe[e + 1] = acc[s][0][3]; }
            if (lane < 4)   { sMe[e] = acc[s][2][0]; sMe[e + 1] = acc[s][2][1]; }
        }
        __syncthreads();

#pragma unroll
        for (int s = 0; s < 4; s++) {
            float* P = acc[s][0]; float* C = acc[s][1]; float* M = acc[s][2];
            float p0s = __shfl_up_sync(FULLM, P[0], 4);
            float p1s = __shfl_up_sync(FULLM, P[1], 4);
            float p2s = __shfl_up_sync(FULLM, P[2], 4);
            float p3s = __shfl_up_sync(FULLM, P[3], 4);
            float p0h = __shfl_sync(FULLM, P[0], 28 + j);
            float p1h = __shfl_sync(FULLM, P[1], 28 + j);
            float m0s = __shfl_down_sync(FULLM, M[0], 4);
            float m1s = __shfl_down_sync(FULLM, M[1], 4);
            float m2s = __shfl_down_sync(FULLM, M[2], 4);
            float m3s = __shfl_down_sync(FULLM, M[3], 4);
            float m2h = __shfl_sync(FULLM, M[2], j);
            float m3h = __shfl_sync(FULLM, M[3], j);
            if (lane < 4) {
                p2s = p0h; p3s = p1h;
                int e = ((s * 2 + riL) * 4 + (q - 1)) * 8 + j * 2;
                p0s = (q > 0) ? sPe[e]     : 0.f;
                p1s = (q > 0) ? sPe[e + 1] : 0.f;
            }
            if (lane >= 28) {
                int jj = lane - 28;
                m0s = m2h; m1s = m3h;
                int e = ((s * 2 + riL) * 4 + (q + 1)) * 8 + jj * 2;
                m2s = (q < 3) ? sMe[e]     : 0.f;
                m3s = (q < 3) ? sMe[e + 1] : 0.f;
            }
            float d0 = C[0] + p0s + m0s;
            float d1 = C[1] + p1s + m1s;
            float d2 = C[2] + p2s + m2s;
            float d3 = C[3] + p3s + m3s;

            int zi = s >> 1, ri = (s & 1) * 2 + riL;
            int mg = (z0 + zi) * 4096 + (y0 + ri) * 64 + 16 * q + (lane >> 2);
            writeOut(out, b, n0,     mg,     d0);
            writeOut(out, b, n0 + 1, mg,     d1);
            writeOut(out, b, n0,     mg + 8, d2);
            writeOut(out, b, n0 + 1, mg + 8, d3);
        }
    }
}

// ---------------------------------------------------------------------------
// Best anchor per GT: u32 truncated-d keys in-block, u64 atomicMin globally
// ---------------------------------------------------------------------------
__global__ __launch_bounds__(256) void best_anchor_kernel(const float* __restrict__ out,
                                                          const float* __restrict__ labels) {
    int b = blockIdx.y, tid = threadIdx.x, lane = tid & 31, warp = tid >> 5;
    int base = blockIdx.x * 1024;
    const float* off = out + OFFSETS_OFF + (size_t)b * 3 * NSPAT;

    float pz[4], py[4], px[4];
#pragma unroll
    for (int i = 0; i < 4; i++) {
        int m = base + i * 256 + tid;
        int zc = m >> 12, yc = (m >> 6) & 63, xc = m & 63;
        pz[i] = (zc + 0.5f) * 32.f + off[m];
        py[i] = (yc + 0.5f) * 32.f + off[NSPAT + m];
        px[i] = (xc + 0.5f) * 32.f + off[2 * NSPAT + m];
    }
    __shared__ float sc[3][64];
    __shared__ unsigned s_red[64][8];
    if (tid < 192) { int d = tid >> 6, n = tid & 63; sc[d][n] = labels[(b * 5 + d) * 64 + n]; }
    __syncthreads();

    for (int n = 0; n < 64; n++) {
        float tz = sc[0][n], ty = sc[1][n], tx = sc[2][n];
        unsigned best = 0xFFFFFFFFu;
#pragma unroll
        for (int i = 0; i < 4; i++) {
            float dz = pz[i] - tz, dy = py[i] - ty, dx = px[i] - tx;
            float d = __fmaf_rn(dz, dz, __fmaf_rn(dy, dy, dx * dx));
            // local idx = i*256+tid in [0,1024); truncate 10 low mantissa bits
            unsigned key = (__float_as_uint(d) & ~1023u) | (unsigned)(i * 256 + tid);
            best = min(best, key);
        }
#pragma unroll
        for (int s = 16; s; s >>= 1)
            best = min(best, __shfl_xor_sync(FULLM, best, s));
        if (lane == 0) s_red[n][warp] = best;
    }
    __syncthreads();
    if (tid < 64) {
        unsigned v = s_red[tid][0];
#pragma unroll
        for (int w = 1; w < 8; w++) v = min(v, s_red[tid][w]);
        unsigned long long key = ((unsigned long long)(v & ~1023u) << 32)
                               | (unsigned)(base + (int)(v & 1023u));
        atomicMin(&g_key[b * 64 + tid], key);
    }
}

// ---------------------------------------------------------------------------
// Focal + reg loss (fast-math transcendentals; double accumulation)
// ---------------------------------------------------------------------------
__device__ __forceinline__ float logsig_f(float x) {
    return fminf(x, 0.f) - __logf(1.f + __expf(-fabsf(x)));
}

__global__ __launch_bounds__(256) void loss_kernel(const float* __restrict__ out,
                                                   const float* __restrict__ labels) {
    int b = blockIdx.y, tid = threadIdx.x;
    int m0 = blockIdx.x * 256, m = m0 + tid;

    __shared__ int   s_match[256];
    __shared__ float s_gt0[4];
    s_match[tid] = -1;
    __syncthreads();
    if (tid < 64) {
        float c = labels[(b * 5 + 3) * 64 + tid];
        if (c >= -0.5f) {
            int bm = (int)(unsigned)(g_key[b * 64 + tid] & 0xFFFFFFFFull);
            if (bm >= m0 && bm < m0 + 256) atomicMax(&s_match[bm - m0], tid);
        }
    }
    if (tid == 128) {
        float sg = labels[(b * 5 + 4) * 64];
        s_gt0[0] = labels[(b * 5 + 0) * 64];
        s_gt0[1] = labels[(b * 5 + 1) * 64];
        s_gt0[2] = labels[(b * 5 + 2) * 64];
        s_gt0[3] = 1.f / (2.f * sg * sg);
    }
    __syncthreads();

    int matched = s_match[tid];
    int assigned = (matched >= 0) ? (int)labels[(b * 5 + 3) * 64 + matched] : -1;

    const float* lg = out + (size_t)b * 5 * NSPAT;
    float csum = 0.f;
#pragma unroll
    for (int c = 0; c < 5; c++) {
        float x = lg[(size_t)c * NSPAT + m];
        float p = 1.f / (1.f + __expf(-x));
        if (c == assigned) { float qq = 1.f - p; csum -= qq * qq * logsig_f(x); }
        else               {                     csum -= p * p * logsig_f(-x); }
    }

    float r = 0.f;
    if (matched < 0) {
        const float* off = out + OFFSETS_OFF + (size_t)b * 3 * NSPAT;
        int z = m >> 12, y = (m >> 6) & 63, x = m & 63;
        float pz = (z + 0.5f) * 32.f + off[m];
        float py = (y + 0.5f) * 32.f + off[NSPAT + m];
        float px = (x + 0.5f) * 32.f + off[2 * NSPAT + m];
        float dz = pz - s_gt0[0], dy = py - s_gt0[1], dx = px - s_gt0[2];
        float d = dz * dz + dy * dy + dx * dx;
        r = 1.f - __expf(-d * s_gt0[3]);
    }

    __shared__ double sd[256];
    sd[tid] = (double)csum + (double)r;
    __syncthreads();
    for (int s = 128; s > 0; s >>= 1) {
        if (tid < s) sd[tid] += sd[tid + s];
        __syncthreads();
    }
    if (tid == 0) atomicAdd(&g_loss[0], sd[0]);
}

__global__ void finalize_kernel(const void* __restrict__ nitems, float* __restrict__ out) {
    long long iv = ((const int*)nitems)[0];
    float     fv = ((const float*)nitems)[0];
    double n = (iv >= 1 && iv <= 1048576) ? (double)iv : (double)fv;
    out[LOSS_OFF] = (float)(g_loss[0] / n);
}

// ---------------------------------------------------------------------------
extern "C" void kernel_launch(void* const* d_in, const int* in_sizes, int n_in,
                              void* d_out, int out_size) {
    const float* feat   = (const float*)d_in[0];
    const float* labels = (const float*)d_in[1];
    const float* cls_w  = (const float*)d_in[2];
    const float* cls_b  = (const float*)d_in[3];
    const float* off_w  = (const float*)d_in[4];
    const float* off_b  = (const float*)d_in[5];
    float* out = (float*)d_out;

    cudaFuncSetAttribute(conv_mma_kernel, cudaFuncAttributeMaxDynamicSharedMemorySize, SM_TOTAL);

    build_tab_kernel<<<7, 256>>>(cls_w, off_w);
    conv_mma_kernel<<<NBLK, 256, SM_TOTAL>>>(feat, cls_b, off_b, out);
    best_anchor_kernel<<<dim3(256, 2), 256>>>(out, labels);
    loss_kernel<<<dim3(1024, 2), 256>>>(out, labels);
    finalize_kernel<<<1, 1>>>(d_in[6], out);
}

// round 13
// speedup vs baseline: 1.4624x; 1.0581x over previous
#include <cuda_runtime.h>
#include <cuda_fp16.h>
#include <math.h>

#define NSPAT (64*64*64)
#define OFFSETS_OFF (2*5*NSPAT)
#define LOSS_OFF (16*NSPAT)

// B fragments: [tap(27)][kcp(2)][lane(32)] -> uint4 {kc lo,hi | kc+1 lo,hi}
__device__ __align__(16) uint4 g_btab[1728];
__device__ unsigned long long g_key[128];
__device__ double g_loss[1];
__device__ unsigned g_tile;
__device__ unsigned g_done;

// ---------------------------------------------------------------------------
// Precompute packed fp16 B fragments once (+ global state init)
// ---------------------------------------------------------------------------
__global__ void build_tab_kernel(const float* __restrict__ cls_w,
                                 const float* __restrict__ off_w) {
    int i = blockIdx.x * 256 + threadIdx.x;     // 0..1791
    if (blockIdx.x == 0) {
        int t = threadIdx.x;
        if (t < 128) g_key[t] = 0xFFFFFFFFFFFFFFFFull;
        if (t == 128) g_loss[0] = 0.0;
        if (t == 129) g_tile = 0u;
        if (t == 130) g_done = 0u;
    }
    if (i >= 1728) return;
    int lane = i & 31, kcp = (i >> 5) & 1, tap = i >> 6;
    int n = lane >> 2, k0 = (lane & 3) * 2;
    const float* w = (n < 5) ? (cls_w + n * 1728) : (off_w + (n - 5) * 1728);
    uint4 r;
    {
        int kk = (2 * kcp) * 16 + k0;
        r.x = (unsigned)__half_as_ushort(__float2half_rn(w[kk * 27 + tap]))
            | ((unsigned)__half_as_ushort(__float2half_rn(w[(kk + 1) * 27 + tap])) << 16);
        r.y = (unsigned)__half_as_ushort(__float2half_rn(w[(kk + 8) * 27 + tap]))
            | ((unsigned)__half_as_ushort(__float2half_rn(w[(kk + 9) * 27 + tap])) << 16);
    }
    {
        int kk = (2 * kcp + 1) * 16 + k0;
        r.z = (unsigned)__half_as_ushort(__float2half_rn(w[kk * 27 + tap]))
            | ((unsigned)__half_as_ushort(__float2half_rn(w[(kk + 1) * 27 + tap])) << 16);
        r.w = (unsigned)__half_as_ushort(__float2half_rn(w[(kk + 8) * 27 + tap]))
            | ((unsigned)__half_as_ushort(__float2half_rn(w[(kk + 9) * 27 + tap])) << 16);
    }
    g_btab[i] = r;
}

// ---------------------------------------------------------------------------
// Fused conv: direct fp32 NCDHW load + fp16 convert + shift-accumulator MMA
// ---------------------------------------------------------------------------
__device__ __forceinline__ void writeOut(float* out, int b, int n, int m, float v) {
    if (n < 5) out[(size_t)(b * 5 + n) * NSPAT + m] = v;
    else       out[OFFSETS_OFF + (size_t)(b * 3 + (n - 5)) * NSPAT + m] = v;
}

#define MMA_F16(ac, a0,a1,a2,a3, b0,b1) \
    asm volatile("mma.sync.aligned.m16n8k16.row.col.f32.f16.f16.f32 " \
        "{%0,%1,%2,%3}, {%4,%5,%6,%7}, {%8,%9}, {%0,%1,%2,%3};" \
        : "+f"(ac[0]), "+f"(ac[1]), "+f"(ac[2]), "+f"(ac[3]) \
        : "r"(a0), "r"(a1), "r"(a2), "r"(a3), "r"(b0), "r"(b1))

#define SM_BUF 8192                 /* 64 voxels * 64ch * 2B */
#define SM_TAB (3*SM_BUF)           /* 24576 */
#define SM_EDGE (SM_TAB + 27648)    /* 52224 */
#define SM_TOTAL (SM_EDGE + 2048 + 16)
#define NTILES 1024
#define NBLK 296
#define FULLM 0xFFFFFFFFu

extern __shared__ unsigned char s_dyn[];

__global__ __launch_bounds__(256, 2) void conv_mma_kernel(
        const float* __restrict__ feat,
        const float* __restrict__ cls_b, const float* __restrict__ off_b,
        float* __restrict__ out) {
    int tid = threadIdx.x, lane = tid & 31, warp = tid >> 5;
    int q = warp & 3, riL = warp >> 2;

    unsigned sbase = (unsigned)__cvta_generic_to_shared(s_dyn);
    const uint4* s_tab = (const uint4*)(s_dyn + SM_TAB);
    float* sPe = (float*)(s_dyn + SM_EDGE);
    float* sMe = (float*)(s_dyn + SM_EDGE + 1024);
    unsigned* s_tile = (unsigned*)(s_dyn + SM_EDGE + 2048);

    {
        uint4* dst = (uint4*)(s_dyn + SM_TAB);
        for (int i = tid; i < 1728; i += 256) dst[i] = g_btab[i];
    }

    int n0 = (lane & 3) * 2;
    float bi0 = (n0 < 5)     ? cls_b[n0]     : off_b[n0 - 5];
    float bi1 = (n0 + 1 < 5) ? cls_b[n0 + 1] : off_b[n0 - 4];

    const float* featW = feat + (size_t)(warp * 8) * NSPAT + 2 * lane;

#define LDG_ROW(ZZ_, YY_, RR_) do { \
    int zp_ = z0 + (ZZ_) - 1, yp_ = y0 + (YY_) - 1; \
    if (((unsigned)zp_ < 64u) & ((unsigned)yp_ < 64u)) { \
        const float* p_ = featW + (size_t)b * 64 * NSPAT + zp_ * 4096 + yp_ * 64; \
        _Pragma("unroll") \
        for (int cc_ = 0; cc_ < 8; cc_++) RR_[cc_] = *(const float2*)(p_ + (size_t)cc_ * NSPAT); \
    } else { \
        _Pragma("unroll") \
        for (int cc_ = 0; cc_ < 8; cc_++) RR_[cc_] = make_float2(0.f, 0.f); \
    } \
} while (0)

#define STS_ROW(BUF_, RR_) do { \
    __half2 h0_[4], h1_[4]; \
    _Pragma("unroll") \
    for (int j_ = 0; j_ < 4; j_++) { \
        h0_[j_] = __floats2half2_rn(RR_[2*j_].x, RR_[2*j_+1].x); \
        h1_[j_] = __floats2half2_rn(RR_[2*j_].y, RR_[2*j_+1].y); \
    } \
    int v0_ = 2 * lane, v1_ = 2 * lane + 1; \
    *(uint4*)(s_dyn + (BUF_) * SM_BUF + (v0_ * 8 + (warp ^ (v0_ & 7))) * 16) = *(uint4*)h0_; \
    *(uint4*)(s_dyn + (BUF_) * SM_BUF + (v1_ * 8 + (warp ^ (v1_ & 7))) * 16) = *(uint4*)h1_; \
} while (0)

    for (;;) {
        if (tid == 0) s_tile[0] = atomicAdd(&g_tile, 1u);
        __syncthreads();
        unsigned t = s_tile[0];
        if (t >= NTILES) break;

        int z0 = (t & 31) * 2;
        int y0 = ((t >> 5) & 15) * 4;
        int b  = t >> 9;

        float acc[4][3][4];
#pragma unroll
        for (int s = 0; s < 4; s++)
#pragma unroll
            for (int j = 0; j < 3; j++) {
                float v0 = (j == 1) ? bi0 : 0.f, v1 = (j == 1) ? bi1 : 0.f;
                acc[s][j][0] = v0; acc[s][j][1] = v1; acc[s][j][2] = v0; acc[s][j][3] = v1;
            }

        float2 rA[8], rB[8];
        LDG_ROW(0, 0, rA);
        LDG_ROW(0, 1, rB);
        STS_ROW(0, rA);
        STS_ROW(1, rB);
        LDG_ROW(0, 2, rA);

#pragma unroll 1
        for (int zz = 0; zz < 4; zz++) {
#pragma unroll
            for (int yy = 0; yy < 6; yy++) {
                __syncthreads();
                if (!(zz == 3 && yy >= 4)) {
                    if (yy & 1) STS_ROW((yy + 2) % 3, rB);
                    else        STS_ROW((yy + 2) % 3, rA);
                }
                if (!(zz == 3 && yy >= 3)) {
                    if (yy & 1) { if (yy + 3 < 6) LDG_ROW(zz, yy + 3, rA); else LDG_ROW(zz + 1, yy - 3, rA); }
                    else        { if (yy + 3 < 6) LDG_ROW(zz, yy + 3, rB); else LDG_ROW(zz + 1, yy - 3, rB); }
                }

                bool active = riL ? (yy >= 1) : (yy <= 4);
                if (active) {
                    unsigned abase = sbase + (unsigned)((yy % 3) * SM_BUF);
#pragma unroll
                    for (int kcp = 0; kcp < 2; kcp++) {
                        int vs = 16 * q + (lane & 15);
                        unsigned ch0 = (unsigned)(4 * kcp + (lane >> 4));
                        unsigned ch1 = ch0 + 2;
                        unsigned adr0 = abase + (unsigned)((vs * 8 + (ch0 ^ (vs & 7))) * 16);
                        unsigned adr1 = abase + (unsigned)((vs * 8 + (ch1 ^ (vs & 7))) * 16);
                        unsigned a0, a1, a2, a3, c0, c1, c2, c3;
                        asm volatile("ldmatrix.sync.aligned.m8n8.x4.shared.b16 {%0,%1,%2,%3}, [%4];"
                            : "=r"(a0), "=r"(a1), "=r"(a2), "=r"(a3) : "r"(adr0));
                        asm volatile("ldmatrix.sync.aligned.m8n8.x4.shared.b16 {%0,%1,%2,%3}, [%4];"
                            : "=r"(c0), "=r"(c1), "=r"(c2), "=r"(c3) : "r"(adr1));
#pragma unroll
                        for (int zi = 0; zi < 2; zi++) {
                            unsigned dz = (unsigned)(zz - zi);
                            if (dz > 2u) continue;
#pragma unroll
                            for (int rih = 0; rih < 2; rih++) {
                                int y = rih * 2 + riL;
                                unsigned dy = (unsigned)(yy - y);
                                if (dy > 2u) continue;
                                int tb = (int)(dz * 9u + dy * 3u);
#pragma unroll
                                for (int dx = 0; dx < 3; dx++) {
                                    uint4 B = s_tab[((tb + dx) * 2 + kcp) * 32 + lane];
                                    MMA_F16(acc[zi * 2 + rih][dx], a0, a1, a2, a3, B.x, B.y);
                                    MMA_F16(acc[zi * 2 + rih][dx], c0, c1, c2, c3, B.z, B.w);
                                }
                            }
                        }
                    }
                }
            }
        }
        __syncthreads();

        int j = lane & 3;
#pragma unroll
        for (int s = 0; s < 4; s++) {
            int e = ((s * 2 + riL) * 4 + q) * 8 + j * 2;
            if (lane >= 28) { sPe[e] = acc[s][0][2]; sPe[e + 1] = acc[s][0][3]; }
            if (lane < 4)   { sMe[e] = acc[s][2][0]; sMe[e + 1] = acc[s][2][1]; }
        }
        __syncthreads();

#pragma unroll
        for (int s = 0; s < 4; s++) {
            float* P = acc[s][0]; float* C = acc[s][1]; float* M = acc[s][2];
            float p0s = __shfl_up_sync(FULLM, P[0], 4);
            float p1s = __shfl_up_sync(FULLM, P[1], 4);
            float p2s = __shfl_up_sync(FULLM, P[2], 4);
            float p3s = __shfl_up_sync(FULLM, P[3], 4);
            float p0h = __shfl_sync(FULLM, P[0], 28 + j);
            float p1h = __shfl_sync(FULLM, P[1], 28 + j);
            float m0s = __shfl_down_sync(FULLM, M[0], 4);
            float m1s = __shfl_down_sync(FULLM, M[1], 4);
            float m2s = __shfl_down_sync(FULLM, M[2], 4);
            float m3s = __shfl_down_sync(FULLM, M[3], 4);
            float m2h = __shfl_sync(FULLM, M[2], j);
            float m3h = __shfl_sync(FULLM, M[3], j);
            if (lane < 4) {
                p2s = p0h; p3s = p1h;
                int e = ((s * 2 + riL) * 4 + (q - 1)) * 8 + j * 2;
                p0s = (q > 0) ? sPe[e]     : 0.f;
                p1s = (q > 0) ? sPe[e + 1] : 0.f;
            }
            if (lane >= 28) {
                int jj = lane - 28;
                m0s = m2h; m1s = m3h;
                int e = ((s * 2 + riL) * 4 + (q + 1)) * 8 + jj * 2;
                m2s = (q < 3) ? sMe[e]     : 0.f;
                m3s = (q < 3) ? sMe[e + 1] : 0.f;
            }
            float d0 = C[0] + p0s + m0s;
            float d1 = C[1] + p1s + m1s;
            float d2 = C[2] + p2s + m2s;
            float d3 = C[3] + p3s + m3s;

            int zi = s >> 1, ri = (s & 1) * 2 + riL;
            int mg = (z0 + zi) * 4096 + (y0 + ri) * 64 + 16 * q + (lane >> 2);
            writeOut(out, b, n0,     mg,     d0);
            writeOut(out, b, n0 + 1, mg,     d1);
            writeOut(out, b, n0,     mg + 8, d2);
            writeOut(out, b, n0 + 1, mg + 8, d3);
        }
    }
}

// ---------------------------------------------------------------------------
// Best anchor per GT: half2 SIMD distances, u16-SIMD min, u64 atomicMin global
// ---------------------------------------------------------------------------
__global__ __launch_bounds__(256) void best_anchor_kernel(const float* __restrict__ out,
                                                          const float* __restrict__ labels) {
    int b = blockIdx.y, tid = threadIdx.x, lane = tid & 31, warp = tid >> 5;
    int base = blockIdx.x * 2048;
    const float* off = out + OFFSETS_OFF + (size_t)b * 3 * NSPAT;

    float pz[8], py[8], px[8];
#pragma unroll
    for (int i = 0; i < 8; i++) {
        int m = base + i * 256 + tid;
        int zc = m >> 12, yc = (m >> 6) & 63, xc = m & 63;
        pz[i] = (zc + 0.5f) * 32.f + off[m];
        py[i] = (yc + 0.5f) * 32.f + off[NSPAT + m];
        px[i] = (xc + 0.5f) * 32.f + off[2 * NSPAT + m];
    }
    // pair (i, i+4): lo = local idx i*256+tid, hi = lo + 1024
    __half2 hz[4], hy[4], hx[4];
#pragma unroll
    for (int i = 0; i < 4; i++) {
        hz[i] = __floats2half2_rn(pz[i], pz[i + 4]);
        hy[i] = __floats2half2_rn(py[i], py[i + 4]);
        hx[i] = __floats2half2_rn(px[i], px[i + 4]);
    }

    __shared__ float sc[3][64];
    __shared__ unsigned s_red[64][8];
    if (tid < 192) { int d = tid >> 6, n = tid & 63; sc[d][n] = labels[(b * 5 + d) * 64 + n]; }
    __syncthreads();

    for (int n = 0; n < 64; n++) {
        __half2 tz2 = __float2half2_rn(sc[0][n]);
        __half2 ty2 = __float2half2_rn(sc[1][n]);
        __half2 tx2 = __float2half2_rn(sc[2][n]);
        unsigned db[4];
#pragma unroll
        for (int i = 0; i < 4; i++) {
            __half2 dz = __hsub2(hz[i], tz2);
            __half2 dy = __hsub2(hy[i], ty2);
            __half2 dx = __hsub2(hx[i], tx2);
            __half2 d2 = __hfma2(dz, dz, __hfma2(dy, dy, __hmul2(dx, dx)));
            db[i] = *(unsigned*)&d2;
        }
        unsigned vm = __vminu2(__vminu2(db[0], db[1]), __vminu2(db[2], db[3]));
        unsigned mlo = vm & 0xFFFFu, mhi = vm >> 16;
        unsigned dmin; int h;
        if (mlo <= mhi) { dmin = mlo; h = 0; } else { dmin = mhi; h = 1; }
        int sh = 16 * h;
        int ii = 3;
        if (((db[2] >> sh) & 0xFFFFu) == dmin) ii = 2;
        if (((db[1] >> sh) & 0xFFFFu) == dmin) ii = 1;
        if (((db[0] >> sh) & 0xFFFFu) == dmin) ii = 0;
        unsigned key = (dmin << 11) | ((unsigned)h << 10) | (unsigned)(ii * 256 + tid);
#pragma unroll
        for (int s = 16; s; s >>= 1)
            key = min(key, __shfl_xor_sync(FULLM, key, s));
        if (lane == 0) s_red[n][warp] = key;
    }
    __syncthreads();
    if (tid < 64) {
        unsigned v = s_red[tid][0];
#pragma unroll
        for (int w = 1; w < 8; w++) v = min(v, s_red[tid][w]);
        unsigned d16 = v >> 11;
        unsigned li  = v & 0x7FFu;
        unsigned long long gk = ((unsigned long long)d16 << 32)
                              | (unsigned)(base + (int)li);
        atomicMin(&g_key[b * 64 + tid], gk);
    }
}

// ---------------------------------------------------------------------------
// Focal + reg loss, 2 anchors/thread; finalize in last block
// ---------------------------------------------------------------------------
__device__ __forceinline__ float logsig_f(float x) {
    return fminf(x, 0.f) - __logf(1.f + __expf(-fabsf(x)));
}

__global__ __launch_bounds__(256) void loss_kernel(const float* __restrict__ out,
                                                   const float* __restrict__ labels,
                                                   const void* __restrict__ nitems) {
    int b = blockIdx.y, tid = threadIdx.x;
    int m0 = blockIdx.x * 512;
    int mA = m0 + tid, mB = m0 + tid + 256;

    __shared__ int   s_match[512];
    __shared__ float s_gt0[4];
    s_match[tid] = -1; s_match[tid + 256] = -1;
    __syncthreads();
    if (tid < 64) {
        float c = labels[(b * 5 + 3) * 64 + tid];
        if (c >= -0.5f) {
            int bm = (int)(unsigned)(g_key[b * 64 + tid] & 0xFFFFFFFFull);
            if (bm >= m0 && bm < m0 + 512) atomicMax(&s_match[bm - m0], tid);
        }
    }
    if (tid == 128) {
        float sg = labels[(b * 5 + 4) * 64];
        s_gt0[0] = labels[(b * 5 + 0) * 64];
        s_gt0[1] = labels[(b * 5 + 1) * 64];
        s_gt0[2] = labels[(b * 5 + 2) * 64];
        s_gt0[3] = 1.f / (2.f * sg * sg);
    }
    __syncthreads();

    int matchA = s_match[tid], matchB = s_match[tid + 256];
    int asgA = (matchA >= 0) ? (int)labels[(b * 5 + 3) * 64 + matchA] : -1;
    int asgB = (matchB >= 0) ? (int)labels[(b * 5 + 3) * 64 + matchB] : -1;

    const float* lg = out + (size_t)b * 5 * NSPAT;
    float csum = 0.f;
#pragma unroll
    for (int c = 0; c < 5; c++) {
        float xA = lg[(size_t)c * NSPAT + mA];
        float xB = lg[(size_t)c * NSPAT + mB];
        float pA = 1.f / (1.f + __expf(-xA));
        float pB = 1.f / (1.f + __expf(-xB));
        if (c == asgA) { float qq = 1.f - pA; csum -= qq * qq * logsig_f(xA); }
        else           {                     csum -= pA * pA * logsig_f(-xA); }
        if (c == asgB) { float qq = 1.f - pB; csum -= qq * qq * logsig_f(xB); }
        else           {                     csum -= pB * pB * logsig_f(-xB); }
    }

    const float* off = out + OFFSETS_OFF + (size_t)b * 3 * NSPAT;
    float r = 0.f;
#pragma unroll
    for (int k = 0; k < 2; k++) {
        int m = (k == 0) ? mA : mB;
        int matched = (k == 0) ? matchA : matchB;
        if (matched < 0) {
            int z = m >> 12, y = (m >> 6) & 63, x = m & 63;
            float pz = (z + 0.5f) * 32.f + off[m];
            float py = (y + 0.5f) * 32.f + off[NSPAT + m];
            float px = (x + 0.5f) * 32.f + off[2 * NSPAT + m];
            float dz = pz - s_gt0[0], dy = py - s_gt0[1], dx = px - s_gt0[2];
            float d = __fmaf_rn(dz, dz, __fmaf_rn(dy, dy, dx * dx));
            r += 1.f - __expf(-d * s_gt0[3]);
        }
    }

    __shared__ double sd[256];
    sd[tid] = (double)csum + (double)r;
    __syncthreads();
    for (int s = 128; s > 0; s >>= 1) {
        if (tid < s) sd[tid] += sd[tid + s];
        __syncthreads();
    }
    __shared__ bool s_last;
    if (tid == 0) {
        atomicAdd(&g_loss[0], sd[0]);
        __threadfence();
        unsigned c = atomicAdd(&g_done, 1u);
        s_last = (c == (512u * 2u - 1u));
    }
    __syncthreads();
    if (s_last && tid == 0) {
        long long iv = ((const int*)nitems)[0];
        float     fv = ((const float*)nitems)[0];
        double n = (iv >= 1 && iv <= 1048576) ? (double)iv : (double)fv;
        ((float*)out)[LOSS_OFF] = (float)(g_loss[0] / n);
    }
}

// ---------------------------------------------------------------------------
extern "C" void kernel_launch(void* const* d_in, const int* in_sizes, int n_in,
                              void* d_out, int out_size) {
    const float* feat   = (const float*)d_in[0];
    const float* labels = (const float*)d_in[1];
    const float* cls_w  = (const float*)d_in[2];
    const float* cls_b  = (const float*)d_in[3];
    const float* off_w  = (const float*)d_in[4];
    const float* off_b  = (const float*)d_in[5];
    float* out = (float*)d_out;

    cudaFuncSetAttribute(conv_mma_kernel, cudaFuncAttributeMaxDynamicSharedMemorySize, SM_TOTAL);

    build_tab_kernel<<<7, 256>>>(cls_w, off_w);
    conv_mma_kernel<<<NBLK, 256, SM_TOTAL>>>(feat, cls_b, off_b, out);
    best_anchor_kernel<<<dim3(128, 2), 256>>>(out, labels);
    loss_kernel<<<dim3(512, 2), 256>>>(out, labels, d_in[6]);
}